// round 6
// baseline (speedup 1.0000x reference)
#include <cuda_runtime.h>
#include <math.h>
#include <stdint.h>

#define NCUT 200000
#define GOI  500
#define BB   512
#define LL   16
#define CC   224
#define GTOT 20000
#define LOG2PI 1.8378770664093453
#define NPART 3
#define SDS   292   // padded per-cut d stride in floats

// dynamic smem bytes for k_main: 4 warps * 8 cuts * SDS floats
#define KMAIN_SMEM (4 * 8 * SDS * 4)

// ---------------- device scratch (zero at load; k_final restores) ----------
__device__ float  g_lw[GOI * LL * CC];
__device__ float4 g_spl[GOI * CC];       // PERMUTED per-step (see k_pergene)
__device__ float  g_S[BB];               // rho partition sums (zero at entry)
__device__ int    g_off[GOI + 1];
__device__ int    g_woff[GOI];
__device__ int4   g_cut[NCUT];           // {x_bits, gl, b, li}
__device__ double g_acc[2];

// ---------------- helpers ----------------
__device__ __forceinline__ unsigned long long pk(float a, float b) {
    unsigned long long r;
    asm("mov.b64 %0, {%1,%2};" : "=l"(r) : "f"(a), "f"(b));
    return r;
}
__device__ __forceinline__ void fma2(unsigned long long& d, unsigned long long a, unsigned long long b) {
    asm("fma.rn.f32x2 %0, %1, %2, %0;" : "+l"(d) : "l"(a), "l"(b));
}
__device__ __forceinline__ int iminmax(int v, int hi) { v = v < 0 ? 0 : v; return v > hi ? hi : v; }

// d-array padded position of float index i
__device__ __forceinline__ int posd1(int i)  { return (i >> 4) * 20 + (i & 15); }
__device__ __forceinline__ int posd2(int i2) { return 160 + (i2 >> 3) * 12 + (i2 & 7); }
__device__ __forceinline__ int posd3(int i3) { return 256 + i3; }
__device__ __forceinline__ int pos4(int i4) {
    if (i4 < 32) return (i4 >> 2) * 20 + ((i4 & 3) << 2);
    if (i4 < 48) return 160 + ((i4 - 32) >> 1) * 12 + ((i4 & 1) << 2);
    return 256 + ((i4 - 48) << 2);
}

// ---------------- K1: fused per-gene precompute + histogram ----------------
__global__ void k_pergene_hist(const int* __restrict__ genes_oi,
                               const float* __restrict__ logit_weight,
                               const float* __restrict__ rho_weight,
                               const float* __restrict__ uh,
                               const float* __restrict__ uw,
                               const int* __restrict__ lci,
                               int n, int G) {
    int bid = blockIdx.x, t = threadIdx.x;
    if (bid >= G) {
        int i = (bid - G) * 128 + t;
        if (i < n) atomicAdd(&g_off[lci[i] % G], 1);
        return;
    }
    int g = bid;
    int gene = genes_oi[g];

    float psum = 0.f;
    const float* lwr = logit_weight + (size_t)gene * (LL * CC);
    for (int i = t; i < LL * CC; i += 128) {
        float v = lwr[i];
        g_lw[g * (LL * CC) + i] = v;
        psum -= 0.5f * v * v;
    }
    if (t < LL) { float v = rho_weight[gene * LL + t]; psum -= 0.5f * v * v; }

    __shared__ float s_red[128];
    __shared__ float s_w[128];
    __shared__ float s_scan[128];

    const int nh_t[3] = {128, 64, 32};
    const int oh_t[3] = {0, 128, 192};
    const int ow_t[3] = {0, 127, 190};
    const float* uhr = uh + (size_t)gene * CC;
    const float* uwr = uw + (size_t)gene * 221;

    for (int s = 0; s < 3; s++) {
        int nh = nh_t[s], nw = nh - 1, oh = oh_t[s], ow = ow_t[s];
        float uwv = (t < nw) ? uwr[ow + t] : -1e30f;
        s_red[t] = uwv; __syncthreads();
        for (int o = 64; o; o >>= 1) { if (t < o) s_red[t] = fmaxf(s_red[t], s_red[t + o]); __syncthreads(); }
        float mx = s_red[0]; __syncthreads();
        float e = (t < nw) ? __expf(uwv - mx) : 0.f;
        s_red[t] = e; __syncthreads();
        for (int o = 64; o; o >>= 1) { if (t < o) s_red[t] += s_red[t + o]; __syncthreads(); }
        float inv = 1.0f / s_red[0]; __syncthreads();
        float w = e * inv;
        s_w[t] = w;
        s_scan[t] = w;
        __syncthreads();
        for (int o = 1; o < 128; o <<= 1) {
            float v = (t >= o) ? s_scan[t - o] : 0.f;
            __syncthreads();
            s_scan[t] += v;
            __syncthreads();
        }
        if (t < nh) {
            float loc = (t == 0) ? 0.f : ((t == nw) ? 1.0f : s_scan[t - 1]);
            float wl = (t >= 1) ? s_w[t - 1] : 0.f;
            float wr = (t <= nw - 1) ? w : 0.f;
            float wwv = 0.5f * (wl + wr);
            float wst = (t < nw) ? w : 0.f;
            int pos;
            if (s == 0)      pos = (t & 15) * 8 + (t >> 4);
            else if (s == 1) pos = 128 + (t & 7) * 8 + (t >> 3);
            else             pos = 192 + (t & 3) * 8 + (t >> 2);
            g_spl[g * CC + pos] = make_float4(uhr[oh + t], wwv, loc, wst);
        }
        __syncthreads();
    }

    s_red[t] = psum; __syncthreads();
    for (int o = 64; o; o >>= 1) { if (t < o) s_red[t] += s_red[t + o]; __syncthreads(); }
    if (t == 0) atomicAdd(&g_acc[1], (double)s_red[0]);
}

// ---------------- K2: scan ----------------
__global__ void k_scan(int G) {
    int t = threadIdx.x, lane = t & 31, w = t >> 5;
    int v = (t < G) ? g_off[t] : 0;
    int s = v;
#pragma unroll
    for (int o = 1; o < 32; o <<= 1) {
        int u = __shfl_up_sync(0xffffffffu, s, o);
        if (lane >= o) s += u;
    }
    __shared__ int ws[16];
    if (lane == 31) ws[w] = s;
    __syncthreads();
    if (w == 0) {
        int x = (lane < 16) ? ws[lane] : 0;
#pragma unroll
        for (int o = 1; o < 16; o <<= 1) {
            int u = __shfl_up_sync(0xffffffffu, x, o);
            if (lane >= o) x += u;
        }
        if (lane < 16) ws[lane] = x;
    }
    __syncthreads();
    int base = (w > 0) ? ws[w - 1] : 0;
    int excl = s + base - v;
    if (t <= G) g_off[t] = excl;
    if (t < G)  g_woff[t] = excl;
}

// ---------------- K3: scatter ----------------
__global__ void k_scatter(const int* __restrict__ lci,
                          const int* __restrict__ lgi,
                          const int* __restrict__ lcgi,
                          const float* __restrict__ coord,
                          int n, int G) {
    int i = blockIdx.x * blockDim.x + threadIdx.x;
    if (i < n) {
        int ci = lci[i];
        int g = ci % G;
        int b = ci / G;
        int p = atomicAdd(&g_woff[g], 1);
        g_cut[p] = make_int4(__float_as_int(coord[i]), lgi[i], b, lcgi[i]);
    }
}

// ---------------- K4: main per-cut kernel ----------------
__global__ void __launch_bounds__(128, 5) k_main(const float* __restrict__ clustering,
                                                 int G) {
    extern __shared__ __align__(16) float smem_dyn[];
    float* s_d = smem_dyn;                  // 4 * 8 * SDS floats
    __shared__ double s_acc[4];
    const unsigned FULL = 0xffffffffu;

    int bid = blockIdx.x, t = threadIdx.x;
    int g = bid / NPART, part = bid - g * NPART;
    int wid = t >> 5, lane = t & 31;
    int c = lane >> 2, sub = lane & 3;      // Phase A roles
    int q = lane >> 3, ll = lane & 7;       // Phase B roles

    const ulonglong2* lwv = (const ulonglong2*)(g_lw + (size_t)g * (LL * CC));

    int s0 = g_off[g], e0 = g_off[g + 1];
    int tot = e0 - s0;
    int seg = (tot + NPART - 1) / NPART;
    int mystart = s0 + part * seg;
    int myend = mystart + seg; if (myend > e0) myend = e0;

    float* sd = s_d + wid * (8 * SDS);
    double acc = 0.0;

    for (int base = mystart + wid * 8; base < myend; base += 32) {
        int nc = myend - base; if (nc > 8) nc = 8;

        // ---- Phase A ----
        int myk = base + c;
        int4 cd = make_int4(0, 0, 0, 0);
        if (myk < myend) cd = __ldg(&g_cut[myk]);

        {
            const float4* cp = (const float4*)(clustering + (size_t)cd.z * LL);
            float4 c0 = __ldg(cp + 0), c1 = __ldg(cp + 1), c2 = __ldg(cp + 2), c3 = __ldg(cp + 3);
            unsigned long long cpk[16];
            cpk[0]  = pk(c0.x, c0.x); cpk[1]  = pk(c0.y, c0.y); cpk[2]  = pk(c0.z, c0.z); cpk[3]  = pk(c0.w, c0.w);
            cpk[4]  = pk(c1.x, c1.x); cpk[5]  = pk(c1.y, c1.y); cpk[6]  = pk(c1.z, c1.z); cpk[7]  = pk(c1.w, c1.w);
            cpk[8]  = pk(c2.x, c2.x); cpk[9]  = pk(c2.y, c2.y); cpk[10] = pk(c2.z, c2.z); cpk[11] = pk(c2.w, c2.w);
            cpk[12] = pk(c3.x, c3.x); cpk[13] = pk(c3.y, c3.y); cpk[14] = pk(c3.z, c3.z); cpk[15] = pk(c3.w, c3.w);

            for (int chk = 0; chk < 14; chk++) {
                int i4 = sub * 14 + chk;
                unsigned long long a01 = 0ull, a23 = 0ull;
#pragma unroll
                for (int l = 0; l < 16; l++) {
                    ulonglong2 v = lwv[l * 56 + i4];
                    fma2(a01, cpk[l], v.x);
                    fma2(a23, cpk[l], v.y);
                }
                *(ulonglong2*)&sd[c * SDS + pos4(i4)] = make_ulonglong2(a01, a23);
            }
        }
        __syncwarp();

        // ---- Phase B: 2 passes of 4 quarter-cuts ----
        for (int p = 0; p < 2; p++) {
            int cc = (p << 2) + q;
            bool live = cc < nc;
            float x = __shfl_sync(FULL, __int_as_float(cd.x), cc << 2);
            int gl   = __shfl_sync(FULL, cd.y, cc << 2);
            const float4* splg = g_spl + (size_t)gl * CC;
            const float* dd = sd + cc * SDS;
            float lad = 0.f;

            // ===== step 1 =====
            {
                const float* dp = dd + ll * 20;
                float4 da = *(const float4*)(dp);
                float4 db = *(const float4*)(dp + 4);
                float4 dc2 = *(const float4*)(dp + 8);
                float4 de = *(const float4*)(dp + 12);
                float dreg[16] = {da.x, da.y, da.z, da.w, db.x, db.y, db.z, db.w,
                                  dc2.x, dc2.y, dc2.z, dc2.w, de.x, de.y, de.z, de.w};
                float h[16], w[16];
                float area = 0.f; int cnt = 0;
#pragma unroll
                for (int j = 0; j < 16; j++) {
                    float4 pj = __ldg(splg + (j << 3) + ll);
                    float hv = __expf(pj.x + dreg[j]);
                    h[j] = hv; w[j] = pj.w;
                    cnt += (x >= pj.z) ? 1 : 0;
                    area = fmaf(hv, pj.y, area);
                }
                cnt += __shfl_xor_sync(FULL, cnt, 1, 8);
                cnt += __shfl_xor_sync(FULL, cnt, 2, 8);
                cnt += __shfl_xor_sync(FULL, cnt, 4, 8);
                int bin = iminmax(cnt - 1, 126);
                float wprev = __shfl_up_sync(FULL, w[15], 1, 8);
                float cdf = 0.f;
                int ib = ll << 4;
                float wim1 = wprev;
#pragma unroll
                for (int j = 0; j < 16; j++) {
                    int i = ib + j;
                    float ct = ((i < bin) ? 0.5f * w[j] : 0.f) + ((i >= 1 && i <= bin) ? 0.5f * wim1 : 0.f);
                    cdf = fmaf(h[j], ct, cdf);
                    wim1 = w[j];
                }
                area += __shfl_xor_sync(FULL, area, 4, 8);
                cdf  += __shfl_xor_sync(FULL, cdf, 4, 8);
                float v = (lane & 4) ? cdf : area;
                v += __shfl_xor_sync(FULL, v, 1, 8);
                v += __shfl_xor_sync(FULL, v, 2, 8);
                float o = __shfl_xor_sync(FULL, v, 4, 8);
                area = (lane & 4) ? o : v;
                cdf  = (lane & 4) ? v : o;

                int b1 = bin + 1;
                float4 spb  = __ldg(splg + ((bin & 15) << 3) + (bin >> 4));
                float4 spb1 = __ldg(splg + ((b1 & 15) << 3) + (b1 >> 4));
                float hl = __expf(spb.x + dd[posd1(bin)]);
                float hr = __expf(spb1.x + dd[posd1(b1)]);
                float inv = __fdividef(1.f, area);
                float alpha = __fdividef(x - spb.z, spb.w);
                float hln = hl * inv, hrn = hr * inv;
                x = (0.5f * (hrn - hln) * alpha + hln) * spb.w * alpha + cdf * inv;
                lad += __logf(fmaf(hrn - hln, alpha, hln));
            }

            // ===== step 2 =====
            {
                const float* dp = dd + 160 + ll * 12;
                float4 da = *(const float4*)(dp);
                float4 db = *(const float4*)(dp + 4);
                float dreg[8] = {da.x, da.y, da.z, da.w, db.x, db.y, db.z, db.w};
                float h[8], w[8];
                float area = 0.f; int cnt = 0;
#pragma unroll
                for (int j = 0; j < 8; j++) {
                    float4 pj = __ldg(splg + 128 + (j << 3) + ll);
                    float hv = __expf(pj.x + dreg[j]);
                    h[j] = hv; w[j] = pj.w;
                    cnt += (x >= pj.z) ? 1 : 0;
                    area = fmaf(hv, pj.y, area);
                }
                cnt += __shfl_xor_sync(FULL, cnt, 1, 8);
                cnt += __shfl_xor_sync(FULL, cnt, 2, 8);
                cnt += __shfl_xor_sync(FULL, cnt, 4, 8);
                int bin = iminmax(cnt - 1, 62);
                float wprev = __shfl_up_sync(FULL, w[7], 1, 8);
                float cdf = 0.f;
                int ib = ll << 3;
                float wim1 = wprev;
#pragma unroll
                for (int j = 0; j < 8; j++) {
                    int i = ib + j;
                    float ct = ((i < bin) ? 0.5f * w[j] : 0.f) + ((i >= 1 && i <= bin) ? 0.5f * wim1 : 0.f);
                    cdf = fmaf(h[j], ct, cdf);
                    wim1 = w[j];
                }
                area += __shfl_xor_sync(FULL, area, 4, 8);
                cdf  += __shfl_xor_sync(FULL, cdf, 4, 8);
                float v = (lane & 4) ? cdf : area;
                v += __shfl_xor_sync(FULL, v, 1, 8);
                v += __shfl_xor_sync(FULL, v, 2, 8);
                float o = __shfl_xor_sync(FULL, v, 4, 8);
                area = (lane & 4) ? o : v;
                cdf  = (lane & 4) ? v : o;

                int b1 = bin + 1;
                float4 spb  = __ldg(splg + 128 + ((bin & 7) << 3) + (bin >> 3));
                float4 spb1 = __ldg(splg + 128 + ((b1 & 7) << 3) + (b1 >> 3));
                float hl = __expf(spb.x + dd[posd2(bin)]);
                float hr = __expf(spb1.x + dd[posd2(b1)]);
                float inv = __fdividef(1.f, area);
                float alpha = __fdividef(x - spb.z, spb.w);
                float hln = hl * inv, hrn = hr * inv;
                x = (0.5f * (hrn - hln) * alpha + hln) * spb.w * alpha + cdf * inv;
                lad += __logf(fmaf(hrn - hln, alpha, hln));
            }

            // ===== step 3 =====
            {
                const float* dp = dd + 256 + (ll << 2);
                float4 da = *(const float4*)(dp);
                float dreg[4] = {da.x, da.y, da.z, da.w};
                float h[4], w[4];
                float area = 0.f; int cnt = 0;
#pragma unroll
                for (int j = 0; j < 4; j++) {
                    float4 pj = __ldg(splg + 192 + (j << 3) + ll);
                    float hv = __expf(pj.x + dreg[j]);
                    h[j] = hv; w[j] = pj.w;
                    cnt += (x >= pj.z) ? 1 : 0;
                    area = fmaf(hv, pj.y, area);
                }
                cnt += __shfl_xor_sync(FULL, cnt, 1, 8);
                cnt += __shfl_xor_sync(FULL, cnt, 2, 8);
                cnt += __shfl_xor_sync(FULL, cnt, 4, 8);
                int bin = iminmax(cnt - 1, 30);
                float wprev = __shfl_up_sync(FULL, w[3], 1, 8);
                float cdf = 0.f;
                int ib = ll << 2;
                float wim1 = wprev;
#pragma unroll
                for (int j = 0; j < 4; j++) {
                    int i = ib + j;
                    float ct = ((i < bin) ? 0.5f * w[j] : 0.f) + ((i >= 1 && i <= bin) ? 0.5f * wim1 : 0.f);
                    cdf = fmaf(h[j], ct, cdf);
                    wim1 = w[j];
                }
                area += __shfl_xor_sync(FULL, area, 4, 8);
                cdf  += __shfl_xor_sync(FULL, cdf, 4, 8);
                float v = (lane & 4) ? cdf : area;
                v += __shfl_xor_sync(FULL, v, 1, 8);
                v += __shfl_xor_sync(FULL, v, 2, 8);
                float o = __shfl_xor_sync(FULL, v, 4, 8);
                area = (lane & 4) ? o : v;
                cdf  = (lane & 4) ? v : o;

                int b1 = bin + 1;
                float4 spb  = __ldg(splg + 192 + ((bin & 3) << 3) + (bin >> 2));
                float4 spb1 = __ldg(splg + 192 + ((b1 & 3) << 3) + (b1 >> 2));
                float hl = __expf(spb.x + dd[posd3(bin)]);
                float hr = __expf(spb1.x + dd[posd3(b1)]);
                float inv = __fdividef(1.f, area);
                float alpha = __fdividef(x - spb.z, spb.w);
                float hln = hl * inv, hrn = hr * inv;
                x = (0.5f * (hrn - hln) * alpha + hln) * spb.w * alpha + cdf * inv;
                lad += __logf(fmaf(hrn - hln, alpha, hln));
            }

            if (live && ll == 0) acc += (double)lad;
        }
        __syncwarp();
    }

    acc += __shfl_xor_sync(FULL, acc, 8);
    acc += __shfl_xor_sync(FULL, acc, 16);
    if (lane == 0) s_acc[wid] = acc;
    __syncthreads();
    if (t == 0) {
        double tt = s_acc[0] + s_acc[1] + s_acc[2] + s_acc[3];
        atomicAdd(&g_acc[0], tt);
    }
}

// ---------------- K5: S[b] = sum_j rho_bias[j] * exp(clustering[b].rho_weight[j]) --
#define JPB 64
__global__ void __launch_bounds__(BB) k_S(const float* __restrict__ clustering,
                                          const float* __restrict__ rho_weight,
                                          const float* __restrict__ rho_bias, int GT) {
    int b = threadIdx.x;
    int j0 = blockIdx.x * JPB;
    const float4* cp = (const float4*)(clustering + (size_t)b * LL);
    float4 c0 = __ldg(cp + 0), c1 = __ldg(cp + 1), c2 = __ldg(cp + 2), c3 = __ldg(cp + 3);
    float s = 0.f;
    int jmax = GT - j0; if (jmax > JPB) jmax = JPB;
    for (int jj = 0; jj < jmax; jj++) {
        int j = j0 + jj;
        const float4* rw = (const float4*)(rho_weight + (size_t)j * LL);
        float4 r0 = __ldg(rw + 0), r1 = __ldg(rw + 1), r2 = __ldg(rw + 2), r3 = __ldg(rw + 3);
        float z = 0.f;
        z = fmaf(c0.x, r0.x, z); z = fmaf(c0.y, r0.y, z); z = fmaf(c0.z, r0.z, z); z = fmaf(c0.w, r0.w, z);
        z = fmaf(c1.x, r1.x, z); z = fmaf(c1.y, r1.y, z); z = fmaf(c1.z, r1.z, z); z = fmaf(c1.w, r1.w, z);
        z = fmaf(c2.x, r2.x, z); z = fmaf(c2.y, r2.y, z); z = fmaf(c2.z, r2.z, z); z = fmaf(c2.w, r2.w, z);
        z = fmaf(c3.x, r3.x, z); z = fmaf(c3.y, r3.y, z); z = fmaf(c3.z, r3.z, z); z = fmaf(c3.w, r3.w, z);
        s = fmaf(__ldg(&rho_bias[j]), __expf(z), s);
    }
    atomicAdd(&g_S[b], s);
}

// ---------------- K6: rho term per cut (recompute z) ----------------
__global__ void k_rho(const int* __restrict__ lcgi,
                      const float* __restrict__ clustering,
                      const float* __restrict__ rho_weight,
                      const float* __restrict__ rho_bias,
                      int n, int GT) {
    int i = blockIdx.x * blockDim.x + threadIdx.x;
    float v = 0.f;
    if (i < n) {
        int li = lcgi[i];
        int row = li / GT;
        int j = li - row * GT;
        const float4* cp = (const float4*)(clustering + (size_t)row * LL);
        const float4* rw = (const float4*)(rho_weight + (size_t)j * LL);
        float4 c0 = __ldg(cp + 0), c1 = __ldg(cp + 1), c2 = __ldg(cp + 2), c3 = __ldg(cp + 3);
        float4 r0 = __ldg(rw + 0), r1 = __ldg(rw + 1), r2 = __ldg(rw + 2), r3 = __ldg(rw + 3);
        float z = 0.f;
        z = fmaf(c0.x, r0.x, z); z = fmaf(c0.y, r0.y, z); z = fmaf(c0.z, r0.z, z); z = fmaf(c0.w, r0.w, z);
        z = fmaf(c1.x, r1.x, z); z = fmaf(c1.y, r1.y, z); z = fmaf(c1.z, r1.z, z); z = fmaf(c1.w, r1.w, z);
        z = fmaf(c2.x, r2.x, z); z = fmaf(c2.y, r2.y, z); z = fmaf(c2.z, r2.z, z); z = fmaf(c2.w, r2.w, z);
        z = fmaf(c3.x, r3.x, z); z = fmaf(c3.y, r3.y, z); z = fmaf(c3.z, r3.z, z); z = fmaf(c3.w, r3.w, z);
        v = __logf(__ldg(&rho_bias[j])) + z - __logf(g_S[row]);
    }
    __shared__ double sd_[256];
    sd_[threadIdx.x] = (double)v;
    __syncthreads();
    for (int o = 128; o; o >>= 1) {
        if (threadIdx.x < o) sd_[threadIdx.x] += sd_[threadIdx.x + o];
        __syncthreads();
    }
    if (threadIdx.x == 0) atomicAdd(&g_acc[0], sd_[0]);
}

// ---------------- K7: finalize + restore ----------------
__global__ void k_final(float* out, int G, int N, float logGT) {
    int t = threadIdx.x;
    if (t == 0) {
        double cnt = (double)G * (double)(LL * CC + LL);
        out[0] = (float)(-g_acc[0] - (double)N * (double)logGT
                         - g_acc[1] + 0.5 * LOG2PI * cnt);
    }
    __syncthreads();
    for (int i = t; i <= G; i += blockDim.x) g_off[i] = 0;
    if (t < BB) g_S[t] = 0.f;
    if (t < 2) g_acc[t] = 0.0;
}

// ---------------- launch ----------------
extern "C" void kernel_launch(void* const* d_in, const int* in_sizes, int n_in,
                              void* d_out, int out_size) {
    const float* clustering    = (const float*)d_in[0];
    const float* coordinates   = (const float*)d_in[1];
    const int*   genes_oi      = (const int*)d_in[2];
    const int*   local_gene_ix = (const int*)d_in[3];
    const int*   lci           = (const int*)d_in[4];
    const int*   lcgi          = (const int*)d_in[5];
    const float* logit_weight  = (const float*)d_in[6];
    const float* rho_weight    = (const float*)d_in[7];
    const float* rho_bias      = (const float*)d_in[8];
    const float* uh            = (const float*)d_in[9];
    const float* uw            = (const float*)d_in[10];

    int N  = in_sizes[1];
    int G  = in_sizes[2];
    int GT = in_sizes[8];

    cudaFuncSetAttribute(k_main, cudaFuncAttributeMaxDynamicSharedMemorySize, KMAIN_SMEM);

    int histBlocks = (N + 127) / 128;
    k_pergene_hist<<<G + histBlocks, 128>>>(genes_oi, logit_weight, rho_weight,
                                            uh, uw, lci, N, G);
    k_scan<<<1, 512>>>(G);
    k_scatter<<<(N + 255) / 256, 256>>>(lci, local_gene_ix, lcgi, coordinates, N, G);
    k_main<<<NPART * G, 128, KMAIN_SMEM>>>(clustering, G);
    k_S<<<(GT + JPB - 1) / JPB, BB>>>(clustering, rho_weight, rho_bias, GT);
    k_rho<<<(N + 255) / 256, 256>>>(lcgi, clustering, rho_weight, rho_bias, N, GT);
    k_final<<<1, 512>>>((float*)d_out, G, N, logf((float)GT));
}

// round 7
// speedup vs baseline: 1.6486x; 1.6486x over previous
#include <cuda_runtime.h>
#include <cuda_bf16.h>
#include <math.h>
#include <stdint.h>

#define NCUT 200000
#define GOI  500
#define BB   512
#define LL   16
#define CC   224
#define GTOT 20000
#define LOG2PI 1.8378770664093453

// ---------------- device scratch (zero at load; k_final restores) ----------
__device__ unsigned short g_d[(size_t)BB * GOI * CC];  // bf16 deltas, 114.7MB
__device__ float4 g_spl[GOI * CC];                     // PERMUTED per-step
__device__ float  g_S[BB];                             // rho partition sums
__device__ double g_acc[2];                            // [0]=lik, [1]=prior

// ---------------- helpers ----------------
__device__ __forceinline__ unsigned long long pk(float a, float b) {
    unsigned long long r;
    asm("mov.b64 %0, {%1,%2};" : "=l"(r) : "f"(a), "f"(b));
    return r;
}
__device__ __forceinline__ void upk(unsigned long long p, float& a, float& b) {
    asm("mov.b64 {%0,%1}, %2;" : "=f"(a), "=f"(b) : "l"(p));
}
__device__ __forceinline__ void fma2(unsigned long long& d, unsigned long long a, unsigned long long b) {
    asm("fma.rn.f32x2 %0, %1, %2, %0;" : "+l"(d) : "l"(a), "l"(b));
}
__device__ __forceinline__ int iminmax(int v, int hi) { v = v < 0 ? 0 : v; return v > hi ? hi : v; }
__device__ __forceinline__ float blo(unsigned u) { return __int_as_float(u << 16); }
__device__ __forceinline__ float bhi(unsigned u) { return __int_as_float(u & 0xffff0000u); }
__device__ __forceinline__ float dsc(const unsigned short* dr, int i) {
    return __int_as_float(((unsigned)__ldg(&dr[i])) << 16);
}
__device__ __forceinline__ unsigned bfpack(unsigned long long p) {
    float a, b; upk(p, a, b);
    __nv_bfloat162 h2 = __floats2bfloat162_rn(a, b);
    return *reinterpret_cast<unsigned*>(&h2);
}

// ---------------- K1: per-gene spline precompute + prior ----------------
__global__ void k_pergene(const int* __restrict__ genes_oi,
                          const float* __restrict__ logit_weight,
                          const float* __restrict__ rho_weight,
                          const float* __restrict__ uh,
                          const float* __restrict__ uw) {
    int g = blockIdx.x, t = threadIdx.x;
    int gene = genes_oi[g];

    float psum = 0.f;
    const float* lwr = logit_weight + (size_t)gene * (LL * CC);
    for (int i = t; i < LL * CC; i += 128) {
        float v = lwr[i];
        psum -= 0.5f * v * v;
    }
    if (t < LL) { float v = rho_weight[gene * LL + t]; psum -= 0.5f * v * v; }

    __shared__ float s_red[128];
    __shared__ float s_w[128];
    __shared__ float s_scan[128];

    const int nh_t[3] = {128, 64, 32};
    const int oh_t[3] = {0, 128, 192};
    const int ow_t[3] = {0, 127, 190};
    const float* uhr = uh + (size_t)gene * CC;
    const float* uwr = uw + (size_t)gene * 221;

    for (int s = 0; s < 3; s++) {
        int nh = nh_t[s], nw = nh - 1, oh = oh_t[s], ow = ow_t[s];
        float uwv = (t < nw) ? uwr[ow + t] : -1e30f;
        s_red[t] = uwv; __syncthreads();
        for (int o = 64; o; o >>= 1) { if (t < o) s_red[t] = fmaxf(s_red[t], s_red[t + o]); __syncthreads(); }
        float mx = s_red[0]; __syncthreads();
        float e = (t < nw) ? __expf(uwv - mx) : 0.f;
        s_red[t] = e; __syncthreads();
        for (int o = 64; o; o >>= 1) { if (t < o) s_red[t] += s_red[t + o]; __syncthreads(); }
        float inv = 1.0f / s_red[0]; __syncthreads();
        float w = e * inv;
        s_w[t] = w;
        s_scan[t] = w;
        __syncthreads();
        for (int o = 1; o < 128; o <<= 1) {
            float v = (t >= o) ? s_scan[t - o] : 0.f;
            __syncthreads();
            s_scan[t] += v;
            __syncthreads();
        }
        if (t < nh) {
            float loc = (t == 0) ? 0.f : ((t == nw) ? 1.0f : s_scan[t - 1]);
            float wl = (t >= 1) ? s_w[t - 1] : 0.f;
            float wr = (t <= nw - 1) ? w : 0.f;
            float wwv = 0.5f * (wl + wr);
            float wst = (t < nw) ? w : 0.f;
            int pos;
            if (s == 0)      pos = (t & 15) * 8 + (t >> 4);
            else if (s == 1) pos = 128 + (t & 7) * 8 + (t >> 3);
            else             pos = 192 + (t & 3) * 8 + (t >> 2);
            g_spl[g * CC + pos] = make_float4(uhr[oh + t], wwv, loc, wst);
        }
        __syncthreads();
    }

    s_red[t] = psum; __syncthreads();
    for (int o = 64; o; o >>= 1) { if (t < o) s_red[t] += s_red[t + o]; __syncthreads(); }
    if (t == 0) atomicAdd(&g_acc[1], (double)s_red[0]);
}

// ---------------- K2: delta GEMM  D[b,g,:] = clustering[b,:] @ lw[g,:,:] -----
// grid (G, B/128), 128 threads. Warp computes 32 b (4 tiles of 8) x 224 c.
__global__ void __launch_bounds__(128) k_gemm(const int* __restrict__ genes_oi,
                                              const float* __restrict__ logit_weight,
                                              const float* __restrict__ clustering,
                                              int G) {
    __shared__ __align__(16) float s_lw[LL * CC];
    __shared__ float s_cl[128 * LL];
    int g = blockIdx.x, bs = blockIdx.y, t = threadIdx.x;
    int gene = genes_oi[g];

    const float* lwr = logit_weight + (size_t)gene * (LL * CC);
    for (int i = t; i < LL * CC; i += 128) s_lw[i] = lwr[i];
    const float* clr = clustering + (size_t)bs * 128 * LL;
    for (int i = t; i < 128 * LL; i += 128) s_cl[i] = clr[i];
    __syncthreads();

    int wid = t >> 5, lane = t & 31;
    bool l4 = lane < 16;

    for (int tile = 0; tile < 4; tile++) {
        int b0 = wid * 32 + tile * 8;
        unsigned long long acc[8][4];
#pragma unroll
        for (int bb = 0; bb < 8; bb++)
#pragma unroll
            for (int k = 0; k < 4; k++) acc[bb][k] = 0ull;

        for (int l = 0; l < LL; l++) {
            const float* lwrow = s_lw + l * CC;
            unsigned long long w0 = *(const unsigned long long*)&lwrow[2 * lane];
            unsigned long long w1 = *(const unsigned long long*)&lwrow[2 * lane + 64];
            unsigned long long w2 = *(const unsigned long long*)&lwrow[2 * lane + 128];
            unsigned long long w3 = l4 ? *(const unsigned long long*)&lwrow[2 * lane + 192] : 0ull;
#pragma unroll
            for (int bb = 0; bb < 8; bb++) {
                float cv = s_cl[(b0 + bb) * LL + l];
                unsigned long long c2 = pk(cv, cv);
                fma2(acc[bb][0], c2, w0);
                fma2(acc[bb][1], c2, w1);
                fma2(acc[bb][2], c2, w2);
                fma2(acc[bb][3], c2, w3);
            }
        }
#pragma unroll
        for (int bb = 0; bb < 8; bb++) {
            int b = bs * 128 + b0 + bb;
            unsigned* out = (unsigned*)(g_d + ((size_t)b * G + g) * CC);
            out[lane]      = bfpack(acc[bb][0]);
            out[lane + 32] = bfpack(acc[bb][1]);
            out[lane + 64] = bfpack(acc[bb][2]);
            if (l4) out[lane + 96] = bfpack(acc[bb][3]);
        }
    }
}

// ---------------- K3: S[b] = sum_j rho_bias[j]*exp(cl[b].rho_w[j]) ----------
#define JPB 64
__global__ void __launch_bounds__(BB) k_S(const float* __restrict__ clustering,
                                          const float* __restrict__ rho_weight,
                                          const float* __restrict__ rho_bias, int GT) {
    int b = threadIdx.x;
    int j0 = blockIdx.x * JPB;
    const float4* cp = (const float4*)(clustering + (size_t)b * LL);
    float4 c0 = __ldg(cp + 0), c1 = __ldg(cp + 1), c2 = __ldg(cp + 2), c3 = __ldg(cp + 3);
    float s = 0.f;
    int jmax = GT - j0; if (jmax > JPB) jmax = JPB;
    for (int jj = 0; jj < jmax; jj++) {
        int j = j0 + jj;
        const float4* rw = (const float4*)(rho_weight + (size_t)j * LL);
        float4 r0 = __ldg(rw + 0), r1 = __ldg(rw + 1), r2 = __ldg(rw + 2), r3 = __ldg(rw + 3);
        float z = 0.f;
        z = fmaf(c0.x, r0.x, z); z = fmaf(c0.y, r0.y, z); z = fmaf(c0.z, r0.z, z); z = fmaf(c0.w, r0.w, z);
        z = fmaf(c1.x, r1.x, z); z = fmaf(c1.y, r1.y, z); z = fmaf(c1.z, r1.z, z); z = fmaf(c1.w, r1.w, z);
        z = fmaf(c2.x, r2.x, z); z = fmaf(c2.y, r2.y, z); z = fmaf(c2.z, r2.z, z); z = fmaf(c2.w, r2.w, z);
        z = fmaf(c3.x, r3.x, z); z = fmaf(c3.y, r3.y, z); z = fmaf(c3.z, r3.z, z); z = fmaf(c3.w, r3.w, z);
        s = fmaf(__ldg(&rho_bias[j]), __expf(z), s);
    }
    atomicAdd(&g_S[b], s);
}

// ---------------- K4: main per-cut spline kernel ----------------
// 128 threads = 4 warps; warp handles 4 cuts (one per 8-lane quarter).
__global__ void __launch_bounds__(128) k_main(const float* __restrict__ coord,
                                              const int* __restrict__ lgi,
                                              const int* __restrict__ lci,
                                              int n) {
    __shared__ double s_acc[4];
    const unsigned FULL = 0xffffffffu;
    int t = threadIdx.x;
    int wid = t >> 5, lane = t & 31;
    int q = lane >> 3, ll = lane & 7;

    int cut = blockIdx.x * 16 + wid * 4 + q;
    bool live = cut < n;
    int cu = live ? cut : (n - 1);

    float x = __ldg(&coord[cu]);
    int gl = __ldg(&lgi[cu]);
    int ci = __ldg(&lci[cu]);

    const float4* splg = g_spl + (size_t)gl * CC;
    const unsigned short* drs = g_d + (size_t)ci * CC;
    const uint4* drow4 = (const uint4*)drs;
    float lad = 0.f;

    // ===== step 1: 128 heights, lane owns i = 16*ll + j =====
    {
        uint4 u0 = __ldg(&drow4[ll * 2]);
        uint4 u1 = __ldg(&drow4[ll * 2 + 1]);
        unsigned wds[8] = {u0.x, u0.y, u0.z, u0.w, u1.x, u1.y, u1.z, u1.w};
        float dreg[16];
#pragma unroll
        for (int p = 0; p < 8; p++) { dreg[2 * p] = blo(wds[p]); dreg[2 * p + 1] = bhi(wds[p]); }
        float h[16], w[16];
        float area = 0.f; int cnt = 0;
#pragma unroll
        for (int j = 0; j < 16; j++) {
            float4 pj = __ldg(splg + (j << 3) + ll);
            float hv = __expf(pj.x + dreg[j]);
            h[j] = hv; w[j] = pj.w;
            cnt += (x >= pj.z) ? 1 : 0;
            area = fmaf(hv, pj.y, area);
        }
        cnt += __shfl_xor_sync(FULL, cnt, 1, 8);
        cnt += __shfl_xor_sync(FULL, cnt, 2, 8);
        cnt += __shfl_xor_sync(FULL, cnt, 4, 8);
        int bin = iminmax(cnt - 1, 126);
        float wprev = __shfl_up_sync(FULL, w[15], 1, 8);
        float cdf = 0.f;
        int ib = ll << 4;
        float wim1 = wprev;
#pragma unroll
        for (int j = 0; j < 16; j++) {
            int i = ib + j;
            float ct = ((i < bin) ? 0.5f * w[j] : 0.f) + ((i >= 1 && i <= bin) ? 0.5f * wim1 : 0.f);
            cdf = fmaf(h[j], ct, cdf);
            wim1 = w[j];
        }
        area += __shfl_xor_sync(FULL, area, 4, 8);
        cdf  += __shfl_xor_sync(FULL, cdf, 4, 8);
        float v = (lane & 4) ? cdf : area;
        v += __shfl_xor_sync(FULL, v, 1, 8);
        v += __shfl_xor_sync(FULL, v, 2, 8);
        float o = __shfl_xor_sync(FULL, v, 4, 8);
        area = (lane & 4) ? o : v;
        cdf  = (lane & 4) ? v : o;

        int b1 = bin + 1;
        float4 spb  = __ldg(splg + ((bin & 15) << 3) + (bin >> 4));
        float4 spb1 = __ldg(splg + ((b1 & 15) << 3) + (b1 >> 4));
        float hl = __expf(spb.x + dsc(drs, bin));
        float hr = __expf(spb1.x + dsc(drs, b1));
        float inv = __fdividef(1.f, area);
        float alpha = __fdividef(x - spb.z, spb.w);
        float hln = hl * inv, hrn = hr * inv;
        x = (0.5f * (hrn - hln) * alpha + hln) * spb.w * alpha + cdf * inv;
        lad += __logf(fmaf(hrn - hln, alpha, hln));
    }

    // ===== step 2: 64 heights, lane owns i = 8*ll + j =====
    {
        uint4 u0 = __ldg(&drow4[16 + ll]);
        unsigned wds[4] = {u0.x, u0.y, u0.z, u0.w};
        float dreg[8];
#pragma unroll
        for (int p = 0; p < 4; p++) { dreg[2 * p] = blo(wds[p]); dreg[2 * p + 1] = bhi(wds[p]); }
        float h[8], w[8];
        float area = 0.f; int cnt = 0;
#pragma unroll
        for (int j = 0; j < 8; j++) {
            float4 pj = __ldg(splg + 128 + (j << 3) + ll);
            float hv = __expf(pj.x + dreg[j]);
            h[j] = hv; w[j] = pj.w;
            cnt += (x >= pj.z) ? 1 : 0;
            area = fmaf(hv, pj.y, area);
        }
        cnt += __shfl_xor_sync(FULL, cnt, 1, 8);
        cnt += __shfl_xor_sync(FULL, cnt, 2, 8);
        cnt += __shfl_xor_sync(FULL, cnt, 4, 8);
        int bin = iminmax(cnt - 1, 62);
        float wprev = __shfl_up_sync(FULL, w[7], 1, 8);
        float cdf = 0.f;
        int ib = ll << 3;
        float wim1 = wprev;
#pragma unroll
        for (int j = 0; j < 8; j++) {
            int i = ib + j;
            float ct = ((i < bin) ? 0.5f * w[j] : 0.f) + ((i >= 1 && i <= bin) ? 0.5f * wim1 : 0.f);
            cdf = fmaf(h[j], ct, cdf);
            wim1 = w[j];
        }
        area += __shfl_xor_sync(FULL, area, 4, 8);
        cdf  += __shfl_xor_sync(FULL, cdf, 4, 8);
        float v = (lane & 4) ? cdf : area;
        v += __shfl_xor_sync(FULL, v, 1, 8);
        v += __shfl_xor_sync(FULL, v, 2, 8);
        float o = __shfl_xor_sync(FULL, v, 4, 8);
        area = (lane & 4) ? o : v;
        cdf  = (lane & 4) ? v : o;

        int b1 = bin + 1;
        float4 spb  = __ldg(splg + 128 + ((bin & 7) << 3) + (bin >> 3));
        float4 spb1 = __ldg(splg + 128 + ((b1 & 7) << 3) + (b1 >> 3));
        float hl = __expf(spb.x + dsc(drs, 128 + bin));
        float hr = __expf(spb1.x + dsc(drs, 128 + b1));
        float inv = __fdividef(1.f, area);
        float alpha = __fdividef(x - spb.z, spb.w);
        float hln = hl * inv, hrn = hr * inv;
        x = (0.5f * (hrn - hln) * alpha + hln) * spb.w * alpha + cdf * inv;
        lad += __logf(fmaf(hrn - hln, alpha, hln));
    }

    // ===== step 3: 32 heights, lane owns i = 4*ll + j =====
    {
        uint2 u0 = __ldg(&((const uint2*)drow4)[48 + ll]);
        float dreg[4] = {blo(u0.x), bhi(u0.x), blo(u0.y), bhi(u0.y)};
        float h[4], w[4];
        float area = 0.f; int cnt = 0;
#pragma unroll
        for (int j = 0; j < 4; j++) {
            float4 pj = __ldg(splg + 192 + (j << 3) + ll);
            float hv = __expf(pj.x + dreg[j]);
            h[j] = hv; w[j] = pj.w;
            cnt += (x >= pj.z) ? 1 : 0;
            area = fmaf(hv, pj.y, area);
        }
        cnt += __shfl_xor_sync(FULL, cnt, 1, 8);
        cnt += __shfl_xor_sync(FULL, cnt, 2, 8);
        cnt += __shfl_xor_sync(FULL, cnt, 4, 8);
        int bin = iminmax(cnt - 1, 30);
        float wprev = __shfl_up_sync(FULL, w[3], 1, 8);
        float cdf = 0.f;
        int ib = ll << 2;
        float wim1 = wprev;
#pragma unroll
        for (int j = 0; j < 4; j++) {
            int i = ib + j;
            float ct = ((i < bin) ? 0.5f * w[j] : 0.f) + ((i >= 1 && i <= bin) ? 0.5f * wim1 : 0.f);
            cdf = fmaf(h[j], ct, cdf);
            wim1 = w[j];
        }
        area += __shfl_xor_sync(FULL, area, 4, 8);
        cdf  += __shfl_xor_sync(FULL, cdf, 4, 8);
        float v = (lane & 4) ? cdf : area;
        v += __shfl_xor_sync(FULL, v, 1, 8);
        v += __shfl_xor_sync(FULL, v, 2, 8);
        float o = __shfl_xor_sync(FULL, v, 4, 8);
        area = (lane & 4) ? o : v;
        cdf  = (lane & 4) ? v : o;

        int b1 = bin + 1;
        float4 spb  = __ldg(splg + 192 + ((bin & 3) << 3) + (bin >> 2));
        float4 spb1 = __ldg(splg + 192 + ((b1 & 3) << 3) + (b1 >> 2));
        float hl = __expf(spb.x + dsc(drs, 192 + bin));
        float hr = __expf(spb1.x + dsc(drs, 192 + b1));
        float inv = __fdividef(1.f, area);
        float alpha = __fdividef(x - spb.z, spb.w);
        float hln = hl * inv, hrn = hr * inv;
        x = (0.5f * (hrn - hln) * alpha + hln) * spb.w * alpha + cdf * inv;
        lad += __logf(fmaf(hrn - hln, alpha, hln));
    }

    double acc = (live && ll == 0) ? (double)lad : 0.0;
    acc += __shfl_xor_sync(FULL, acc, 8);
    acc += __shfl_xor_sync(FULL, acc, 16);
    if (lane == 0) s_acc[wid] = acc;
    __syncthreads();
    if (t == 0) {
        double tt = s_acc[0] + s_acc[1] + s_acc[2] + s_acc[3];
        atomicAdd(&g_acc[0], tt);
    }
}

// ---------------- K5: rho term per cut ----------------
__global__ void k_rho(const int* __restrict__ lcgi,
                      const float* __restrict__ clustering,
                      const float* __restrict__ rho_weight,
                      const float* __restrict__ rho_bias,
                      int n, int GT) {
    int i = blockIdx.x * blockDim.x + threadIdx.x;
    float v = 0.f;
    if (i < n) {
        int li = lcgi[i];
        int row = li / GT;
        int j = li - row * GT;
        const float4* cp = (const float4*)(clustering + (size_t)row * LL);
        const float4* rw = (const float4*)(rho_weight + (size_t)j * LL);
        float4 c0 = __ldg(cp + 0), c1 = __ldg(cp + 1), c2 = __ldg(cp + 2), c3 = __ldg(cp + 3);
        float4 r0 = __ldg(rw + 0), r1 = __ldg(rw + 1), r2 = __ldg(rw + 2), r3 = __ldg(rw + 3);
        float z = 0.f;
        z = fmaf(c0.x, r0.x, z); z = fmaf(c0.y, r0.y, z); z = fmaf(c0.z, r0.z, z); z = fmaf(c0.w, r0.w, z);
        z = fmaf(c1.x, r1.x, z); z = fmaf(c1.y, r1.y, z); z = fmaf(c1.z, r1.z, z); z = fmaf(c1.w, r1.w, z);
        z = fmaf(c2.x, r2.x, z); z = fmaf(c2.y, r2.y, z); z = fmaf(c2.z, r2.z, z); z = fmaf(c2.w, r2.w, z);
        z = fmaf(c3.x, r3.x, z); z = fmaf(c3.y, r3.y, z); z = fmaf(c3.z, r3.z, z); z = fmaf(c3.w, r3.w, z);
        v = __logf(__ldg(&rho_bias[j])) + z - __logf(g_S[row]);
    }
    __shared__ double sd_[256];
    sd_[threadIdx.x] = (double)v;
    __syncthreads();
    for (int o = 128; o; o >>= 1) {
        if (threadIdx.x < o) sd_[threadIdx.x] += sd_[threadIdx.x + o];
        __syncthreads();
    }
    if (threadIdx.x == 0) atomicAdd(&g_acc[0], sd_[0]);
}

// ---------------- K6: finalize + restore ----------------
__global__ void k_final(float* out, int G, int N, float logGT) {
    int t = threadIdx.x;
    if (t == 0) {
        double cnt = (double)G * (double)(LL * CC + LL);
        out[0] = (float)(-g_acc[0] - (double)N * (double)logGT
                         - g_acc[1] + 0.5 * LOG2PI * cnt);
    }
    __syncthreads();
    for (int i = t; i < BB; i += blockDim.x) g_S[i] = 0.f;
    if (t < 2) g_acc[t] = 0.0;
}

// ---------------- launch ----------------
extern "C" void kernel_launch(void* const* d_in, const int* in_sizes, int n_in,
                              void* d_out, int out_size) {
    const float* clustering    = (const float*)d_in[0];
    const float* coordinates   = (const float*)d_in[1];
    const int*   genes_oi      = (const int*)d_in[2];
    const int*   local_gene_ix = (const int*)d_in[3];
    const int*   lci           = (const int*)d_in[4];
    const int*   lcgi          = (const int*)d_in[5];
    const float* logit_weight  = (const float*)d_in[6];
    const float* rho_weight    = (const float*)d_in[7];
    const float* rho_bias      = (const float*)d_in[8];
    const float* uh            = (const float*)d_in[9];
    const float* uw            = (const float*)d_in[10];

    int N  = in_sizes[1];
    int G  = in_sizes[2];
    int B  = in_sizes[0] / LL;
    int GT = in_sizes[8];

    k_pergene<<<G, 128>>>(genes_oi, logit_weight, rho_weight, uh, uw);
    k_gemm<<<dim3(G, B / 128), 128>>>(genes_oi, logit_weight, clustering, G);
    k_S<<<(GT + JPB - 1) / JPB, BB>>>(clustering, rho_weight, rho_bias, GT);
    k_main<<<(N + 15) / 16, 128>>>(coordinates, local_gene_ix, lci, N);
    k_rho<<<(N + 255) / 256, 256>>>(lcgi, clustering, rho_weight, rho_bias, N, GT);
    k_final<<<1, 512>>>((float*)d_out, G, N, logf((float)GT));
}